// round 1
// baseline (speedup 1.0000x reference)
#include <cuda_runtime.h>
#include <cstdint>

#define B_ 4
#define N_ 4096
#define F_ 64

#define BM 128
#define BK 32
#define SA_STRIDE 36          // 32 + 4 pad -> conflict-free frag loads
#define ST_STRIDE 72          // 64 + 8 pad
#define SA_CH (BM * SA_STRIDE)   // 4608 floats per chain
#define ST_CH (BK * ST_STRIDE)   // 2304 floats per chain
#define SMEM_FLOATS (3 * SA_CH + 3 * ST_CH)   // 20736
#define SMEM_BYTES (SMEM_FLOATS * 4)          // 82944

// Scratch: T[c][b] = round_tf32(X[b] @ w_c), 3*4*4096*64 fp32 = 12.6 MB
__device__ float g_T[3][B_][N_ * F_];

// Round-half-up into the tf32-kept bits: hardware truncates low 13 bits of
// each mma operand, so +0x1000 turns truncation into (nearly) unbiased rounding.
__device__ __forceinline__ float rnd_tf32(float x) {
    uint32_t u = __float_as_uint(x) + 0x1000u;
    return __uint_as_float(u);
}

// ---------------------------------------------------------------------------
// Kernel 1: T[c][b] = X[b] @ w_c, output rounded for tf32 consumption.
// grid (64, 4, 3), block 256. Each block: 64 rows x 64 cols of one (b,c).
// ---------------------------------------------------------------------------
__global__ void __launch_bounds__(256)
compute_T_kernel(const float* __restrict__ X,
                 const float* __restrict__ w0,
                 const float* __restrict__ w1,
                 const float* __restrict__ w2) {
    const int c = blockIdx.z;
    const int b = blockIdx.y;
    const int rowBase = blockIdx.x * 64;
    const float* w = (c == 0) ? w0 : (c == 1) ? w1 : w2;

    __shared__ float sX[64 * 68];
    __shared__ float sW[64 * 68];

    const int tid = threadIdx.x;
    {
        const int q = tid & 15;        // float4 index within 64-float row
        const int r = tid >> 4;        // 0..15
        #pragma unroll
        for (int j = 0; j < 4; j++) {
            const int row = r + 16 * j;
            float4 vx = *(const float4*)(X + ((size_t)b * N_ + rowBase + row) * F_ + q * 4);
            *(float4*)(sX + row * 68 + q * 4) = vx;
            float4 vw = *(const float4*)(w + (size_t)row * F_ + q * 4);
            *(float4*)(sW + row * 68 + q * 4) = vw;
        }
    }
    __syncthreads();

    const int row = tid >> 2;          // 0..63 local row
    const int g0  = (tid & 3) * 16;    // 16 output cols per thread

    float acc[16];
    #pragma unroll
    for (int i = 0; i < 16; i++) acc[i] = 0.f;

    #pragma unroll 8
    for (int f = 0; f < 64; f++) {
        const float x = sX[row * 68 + f];
        #pragma unroll
        for (int j = 0; j < 4; j++) {
            float4 wv = *(const float4*)(sW + f * 68 + g0 + j * 4);
            acc[j * 4 + 0] += x * wv.x;
            acc[j * 4 + 1] += x * wv.y;
            acc[j * 4 + 2] += x * wv.z;
            acc[j * 4 + 3] += x * wv.w;
        }
    }

    float* Tp = g_T[c][b] + (size_t)(rowBase + row) * F_ + g0;
    #pragma unroll
    for (int j = 0; j < 4; j++) {
        float4 o;
        o.x = rnd_tf32(acc[j * 4 + 0]);
        o.y = rnd_tf32(acc[j * 4 + 1]);
        o.z = rnd_tf32(acc[j * 4 + 2]);
        o.w = rnd_tf32(acc[j * 4 + 3]);
        *(float4*)(Tp + j * 4) = o;
    }
}

// ---------------------------------------------------------------------------
// Kernel 2: Y[b] = relu(A0@T0 + A1@T1 + A2@T2).
// grid (32, 4), block 256 (8 warps: 4 along M x 2 along N).
// Block tile 128x64, K-tile 32, register-double-buffered global loads,
// tf32 mma.sync m16n8k8 with fp32 accumulation shared across the 3 chains.
// ---------------------------------------------------------------------------
__global__ void __launch_bounds__(256, 1)
gnn_main_kernel(const float* __restrict__ A0,
                const float* __restrict__ A1,
                const float* __restrict__ A2,
                float* __restrict__ Y) {
    const int b = blockIdx.y;
    const int rowBase = blockIdx.x * BM;

    const float* Ap[3];
    Ap[0] = A0 + (size_t)b * N_ * N_;
    Ap[1] = A1 + (size_t)b * N_ * N_;
    Ap[2] = A2 + (size_t)b * N_ * N_;

    const int tid  = threadIdx.x;
    const int lane = tid & 31;
    const int warp = tid >> 5;
    const int warpM = warp >> 1;   // 0..3 -> 32 rows each
    const int warpN = warp & 1;    // 0..1 -> 32 cols each

    extern __shared__ float smem[];
    float* sA = smem;                 // [3][128][36]
    float* sT = smem + 3 * SA_CH;     // [3][32][72]

    // global-load thread mapping (coalesced float4)
    const int aq = tid & 7;          // A: col quad 0..7 (32 floats/row)
    const int ar = tid >> 3;         // A: row group 0..31
    const int tq = tid & 15;         // T: col quad 0..15 (64 floats/row)
    const int tr = tid >> 4;         // T: row group 0..15

    float4 regA[3][4];
    float4 regT[3][2];

    // prefetch tile 0
    #pragma unroll
    for (int c = 0; c < 3; c++) {
        const float* base = Ap[c] + (size_t)rowBase * N_;
        #pragma unroll
        for (int j = 0; j < 4; j++)
            regA[c][j] = *(const float4*)(base + (size_t)(ar + 32 * j) * N_ + aq * 4);
        const float* tb = g_T[c][b];
        #pragma unroll
        for (int j = 0; j < 2; j++)
            regT[c][j] = *(const float4*)(tb + (size_t)(tr + 16 * j) * F_ + tq * 4);
    }

    float acc[2][4][4];
    #pragma unroll
    for (int mt = 0; mt < 2; mt++)
        #pragma unroll
        for (int nt = 0; nt < 4; nt++)
            #pragma unroll
            for (int i = 0; i < 4; i++) acc[mt][nt][i] = 0.f;

    const int NKT = N_ / BK;   // 128

    for (int kt = 0; kt < NKT; kt++) {
        // store current tile to smem (round A into tf32-safe bits here)
        #pragma unroll
        for (int c = 0; c < 3; c++) {
            #pragma unroll
            for (int j = 0; j < 4; j++) {
                float4 v = regA[c][j];
                v.x = rnd_tf32(v.x);
                v.y = rnd_tf32(v.y);
                v.z = rnd_tf32(v.z);
                v.w = rnd_tf32(v.w);
                *(float4*)(sA + c * SA_CH + (ar + 32 * j) * SA_STRIDE + aq * 4) = v;
            }
            #pragma unroll
            for (int j = 0; j < 2; j++)
                *(float4*)(sT + c * ST_CH + (tr + 16 * j) * ST_STRIDE + tq * 4) = regT[c][j];
        }
        __syncthreads();

        // prefetch next tile into registers (overlaps with mma below)
        if (kt + 1 < NKT) {
            const int k0 = (kt + 1) * BK;
            #pragma unroll
            for (int c = 0; c < 3; c++) {
                const float* base = Ap[c] + (size_t)rowBase * N_ + k0;
                #pragma unroll
                for (int j = 0; j < 4; j++)
                    regA[c][j] = *(const float4*)(base + (size_t)(ar + 32 * j) * N_ + aq * 4);
                const float* tb = g_T[c][b] + (size_t)k0 * F_;
                #pragma unroll
                for (int j = 0; j < 2; j++)
                    regT[c][j] = *(const float4*)(tb + (size_t)(tr + 16 * j) * F_ + tq * 4);
            }
        }

        // compute: 4 k-steps x 3 chains x (2 Mtiles x 4 Ntiles) mma
        #pragma unroll
        for (int ks = 0; ks < 4; ks++) {
            const int k0 = ks * 8 + (lane & 3);
            #pragma unroll
            for (int c = 0; c < 3; c++) {
                uint32_t afr[2][4];
                #pragma unroll
                for (int mt = 0; mt < 2; mt++) {
                    const int r0 = warpM * 32 + mt * 16 + (lane >> 2);
                    const float* pa = sA + c * SA_CH + r0 * SA_STRIDE + k0;
                    afr[mt][0] = __float_as_uint(pa[0]);
                    afr[mt][1] = __float_as_uint(pa[8 * SA_STRIDE]);
                    afr[mt][2] = __float_as_uint(pa[4]);
                    afr[mt][3] = __float_as_uint(pa[8 * SA_STRIDE + 4]);
                }
                #pragma unroll
                for (int nt = 0; nt < 4; nt++) {
                    const int n0 = warpN * 32 + nt * 8 + (lane >> 2);
                    const float* pt = sT + c * ST_CH + k0 * ST_STRIDE + n0;
                    const uint32_t b0 = __float_as_uint(pt[0]);
                    const uint32_t b1 = __float_as_uint(pt[4 * ST_STRIDE]);
                    #pragma unroll
                    for (int mt = 0; mt < 2; mt++) {
                        asm volatile(
                            "mma.sync.aligned.m16n8k8.row.col.f32.tf32.tf32.f32 "
                            "{%0,%1,%2,%3}, {%4,%5,%6,%7}, {%8,%9}, {%0,%1,%2,%3};\n"
                            : "+f"(acc[mt][nt][0]), "+f"(acc[mt][nt][1]),
                              "+f"(acc[mt][nt][2]), "+f"(acc[mt][nt][3])
                            : "r"(afr[mt][0]), "r"(afr[mt][1]),
                              "r"(afr[mt][2]), "r"(afr[mt][3]),
                              "r"(b0), "r"(b1));
                    }
                }
            }
        }
        __syncthreads();
    }

    // epilogue: relu + store (fragment layout: c0/c1 row r, c2/c3 row r+8)
    #pragma unroll
    for (int mt = 0; mt < 2; mt++) {
        #pragma unroll
        for (int nt = 0; nt < 4; nt++) {
            const int r0  = rowBase + warpM * 32 + mt * 16 + (lane >> 2);
            const int col = warpN * 32 + nt * 8 + (lane & 3) * 2;
            float2 v0 = make_float2(fmaxf(acc[mt][nt][0], 0.f),
                                    fmaxf(acc[mt][nt][1], 0.f));
            float2 v1 = make_float2(fmaxf(acc[mt][nt][2], 0.f),
                                    fmaxf(acc[mt][nt][3], 0.f));
            *(float2*)(Y + ((size_t)b * N_ + r0) * F_ + col)     = v0;
            *(float2*)(Y + ((size_t)b * N_ + r0 + 8) * F_ + col) = v1;
        }
    }
}

// ---------------------------------------------------------------------------
extern "C" void kernel_launch(void* const* d_in, const int* in_sizes, int n_in,
                              void* d_out, int out_size) {
    (void)in_sizes; (void)n_in; (void)out_size;
    const float* X  = (const float*)d_in[0];
    const float* A0 = (const float*)d_in[1];
    const float* A1 = (const float*)d_in[2];
    const float* A2 = (const float*)d_in[3];
    const float* w0 = (const float*)d_in[4];
    const float* w1 = (const float*)d_in[5];
    const float* w2 = (const float*)d_in[6];
    float* Y = (float*)d_out;

    dim3 g1(N_ / 64, B_, 3);
    compute_T_kernel<<<g1, 256>>>(X, w0, w1, w2);

    cudaFuncSetAttribute(gnn_main_kernel,
                         cudaFuncAttributeMaxDynamicSharedMemorySize, SMEM_BYTES);
    dim3 g2(N_ / BM, B_);
    gnn_main_kernel<<<g2, 256, SMEM_BYTES>>>(A0, A1, A2, Y);
}